// round 9
// baseline (speedup 1.0000x reference)
#include <cuda_runtime.h>
#include <cuda_bf16.h>
#include <cstdint>

// LRML: out[b] = -|| ue + rel - ie ||^2
// 2 lanes/row, 16 rows/warp, 1024 one-warp blocks (R8 winner), with the
// shared-memory weight staging REMOVED: W_att/memory (2.5KB, fixed
// addresses) are read directly via __ldg and stay L1-resident. This
// removes 20 LDG + 20 STS + syncwarp from between the id load and the
// gather issue, shortening the per-warp critical chain:
//    ids (LDG) -> 8 gather LDGs -> compute (weights from L1).

#define D 32
#define M 10
#define THREADS 32
#define ROWS_PER_WARP 16

__global__ __launch_bounds__(THREADS)
void lrml_kernel(const int* __restrict__ user_ids,
                 const int* __restrict__ item_ids,
                 const float* __restrict__ user_emb,
                 const float* __restrict__ item_emb,
                 const float* __restrict__ W_att,
                 const float* __restrict__ memory,
                 float* __restrict__ out,
                 int B)
{
    const int lane = threadIdx.x & 31;
    const int p    = lane & 1;        // which 16-dim half
    const int r    = lane >> 1;       // row within warp (0..15)

    int row = blockIdx.x * ROWS_PER_WARP + r;
    const bool valid = (row < B);
    if (row >= B) row = B - 1;

    // ids (coalesced, L2-warm across graph replays)
    const int uid = __ldg(&user_ids[row]);
    const int iid = __ldg(&item_ids[row]);

    // Gathers issue immediately after ids resolve: each lane reads its
    // 64B half-row from each table (4x LDG.128); both halves of a row
    // share one 128B line.
    const float4* up = (const float4*)(user_emb + (size_t)uid * D + p * 16);
    const float4* ip = (const float4*)(item_emb + (size_t)iid * D + p * 16);
    const float4 u0 = __ldg(up);
    const float4 u1 = __ldg(up + 1);
    const float4 u2 = __ldg(up + 2);
    const float4 u3 = __ldg(up + 3);
    const float4 i0 = __ldg(ip);
    const float4 i1 = __ldg(ip + 1);
    const float4 i2 = __ldg(ip + 2);
    const float4 i3 = __ldg(ip + 3);

    float ue[16] = {u0.x,u0.y,u0.z,u0.w, u1.x,u1.y,u1.z,u1.w,
                    u2.x,u2.y,u2.z,u2.w, u3.x,u3.y,u3.z,u3.w};
    float ie[16] = {i0.x,i0.y,i0.z,i0.w, i1.x,i1.y,i1.z,i1.w,
                    i2.x,i2.y,i2.z,i2.w, i3.x,i3.y,i3.z,i3.w};

    // max_norm=1 renorm (reduction = 1 shfl across the lane pair)
    float us = 0.f, is = 0.f;
    #pragma unroll
    for (int j = 0; j < 16; j++) { us = fmaf(ue[j], ue[j], us); is = fmaf(ie[j], ie[j], is); }
    us += __shfl_xor_sync(0xFFFFFFFFu, us, 1);
    is += __shfl_xor_sync(0xFFFFFFFFu, is, 1);
    const float un = sqrtf(us), in = sqrtf(is);
    const float uscale = (un > 1.0f) ? (1.0f / un) : 1.0f;
    const float iscale = (in > 1.0f) ? (1.0f / in) : 1.0f;
    #pragma unroll
    for (int j = 0; j < 16; j++) { ue[j] *= uscale; ie[j] *= iscale; }

    float joint[16];
    #pragma unroll
    for (int j = 0; j < 16; j++) joint[j] = ue[j] * ie[j];

    // scores[m] = joint . W_att[m]; weights read straight from L1-hot
    // global (2 distinct 16B addresses per instruction).
    const float4* Wv = (const float4*)W_att + p * 4;   // lane's half of row m at Wv + m*8
    float sc[M];
    #pragma unroll
    for (int m = 0; m < M; m++) {
        const float4 w0 = __ldg(Wv + m * 8 + 0);
        const float4 w1 = __ldg(Wv + m * 8 + 1);
        const float4 w2 = __ldg(Wv + m * 8 + 2);
        const float4 w3 = __ldg(Wv + m * 8 + 3);
        float a = joint[0] * w0.x;
        float b = joint[1] * w0.y;
        a = fmaf(joint[2],  w0.z, a);
        b = fmaf(joint[3],  w0.w, b);
        a = fmaf(joint[4],  w1.x, a);
        b = fmaf(joint[5],  w1.y, b);
        a = fmaf(joint[6],  w1.z, a);
        b = fmaf(joint[7],  w1.w, b);
        a = fmaf(joint[8],  w2.x, a);
        b = fmaf(joint[9],  w2.y, b);
        a = fmaf(joint[10], w2.z, a);
        b = fmaf(joint[11], w2.w, b);
        a = fmaf(joint[12], w3.x, a);
        b = fmaf(joint[13], w3.y, b);
        a = fmaf(joint[14], w3.z, a);
        b = fmaf(joint[15], w3.w, b);
        float s = a + b;
        s += __shfl_xor_sync(0xFFFFFFFFu, s, 1);
        sc[m] = s;
    }

    // softmax over M=10, redundantly in both lanes of the pair
    float mx = sc[0];
    #pragma unroll
    for (int m = 1; m < M; m++) mx = fmaxf(mx, sc[m]);
    float denom = 0.0f;
    #pragma unroll
    for (int m = 0; m < M; m++) { sc[m] = __expf(sc[m] - mx); denom += sc[m]; }
    const float inv_denom = 1.0f / denom;

    // rel[j] = sum_m sc[m] * memory[m][p*16+j]; normalization folded into dist
    const float4* Mv = (const float4*)memory + p * 4;
    float rel[16];
    #pragma unroll
    for (int j = 0; j < 16; j++) rel[j] = 0.0f;
    #pragma unroll
    for (int m = 0; m < M; m++) {
        const float4 m0 = __ldg(Mv + m * 8 + 0);
        const float4 m1 = __ldg(Mv + m * 8 + 1);
        const float4 m2 = __ldg(Mv + m * 8 + 2);
        const float4 m3 = __ldg(Mv + m * 8 + 3);
        const float s = sc[m];
        rel[0]  = fmaf(s, m0.x, rel[0]);
        rel[1]  = fmaf(s, m0.y, rel[1]);
        rel[2]  = fmaf(s, m0.z, rel[2]);
        rel[3]  = fmaf(s, m0.w, rel[3]);
        rel[4]  = fmaf(s, m1.x, rel[4]);
        rel[5]  = fmaf(s, m1.y, rel[5]);
        rel[6]  = fmaf(s, m1.z, rel[6]);
        rel[7]  = fmaf(s, m1.w, rel[7]);
        rel[8]  = fmaf(s, m2.x, rel[8]);
        rel[9]  = fmaf(s, m2.y, rel[9]);
        rel[10] = fmaf(s, m2.z, rel[10]);
        rel[11] = fmaf(s, m2.w, rel[11]);
        rel[12] = fmaf(s, m3.x, rel[12]);
        rel[13] = fmaf(s, m3.y, rel[13]);
        rel[14] = fmaf(s, m3.z, rel[14]);
        rel[15] = fmaf(s, m3.w, rel[15]);
    }

    float dist = 0.0f;
    #pragma unroll
    for (int j = 0; j < 16; j++) {
        const float diff = fmaf(rel[j], inv_denom, ue[j] - ie[j]);
        dist = fmaf(diff, diff, dist);
    }
    dist += __shfl_xor_sync(0xFFFFFFFFu, dist, 1);

    if (p == 0 && valid) out[row] = -dist;
}

extern "C" void kernel_launch(void* const* d_in, const int* in_sizes, int n_in,
                              void* d_out, int out_size)
{
    const int*   user_ids = (const int*)  d_in[0];
    const int*   item_ids = (const int*)  d_in[1];
    const float* user_emb = (const float*)d_in[2];
    const float* item_emb = (const float*)d_in[3];
    const float* W_att    = (const float*)d_in[4];
    const float* memory   = (const float*)d_in[5];
    float*       out      = (float*)d_out;

    const int B = in_sizes[0];
    const int grid = (B + ROWS_PER_WARP - 1) / ROWS_PER_WARP;  // 1024
    lrml_kernel<<<grid, THREADS>>>(user_ids, item_ids, user_emb, item_emb,
                                   W_att, memory, out, B);
}